// round 2
// baseline (speedup 1.0000x reference)
#include <cuda_runtime.h>
#include <cstddef>

#define N_NODES 100000
#define N_EDGES 1600000
#define IN_CH   256
#define HID     128
#define OUT_CH  64

// ---------------- scratch (no allocs allowed) ----------------
__device__ int   g_cnt[N_NODES];
__device__ int   g_rowptr[N_NODES + 1];
__device__ int   g_part[128];
__device__ int   g_col[N_EDGES];
__device__ float g_dinv[N_NODES];
__device__ float g_xw[(size_t)N_NODES * HID];     // (x@W1) * dinv[row]
__device__ float g_h [(size_t)N_NODES * HID];     // relu(layer1)
__device__ float g_hw[(size_t)N_NODES * OUT_CH];  // (h@W2) * dinv[row]

// ---------------- degree / CSR build ----------------
__global__ void k_zero_cnt() {
    int i = blockIdx.x * blockDim.x + threadIdx.x;
    if (i < N_NODES) g_cnt[i] = 0;
}

__global__ void k_hist(const int* __restrict__ ei) {
    int e = blockIdx.x * blockDim.x + threadIdx.x;
    if (e < N_EDGES) {
        int dst = ei[N_EDGES + e];
        atomicAdd(&g_cnt[dst], 1);
    }
}

__global__ void k_dinv() {
    int i = blockIdx.x * blockDim.x + threadIdx.x;
    if (i < N_NODES) g_dinv[i] = rsqrtf((float)g_cnt[i] + 1.0f);  // +1 self loop
}

__global__ void k_scan1() {
    __shared__ int warpsum[32];
    int i = blockIdx.x * 1024 + threadIdx.x;
    int lane = threadIdx.x & 31, wid = threadIdx.x >> 5;
    int x = (i < N_NODES) ? g_cnt[i] : 0;
    #pragma unroll
    for (int d = 1; d < 32; d <<= 1) {
        int y = __shfl_up_sync(0xFFFFFFFFu, x, d);
        if (lane >= d) x += y;
    }
    if (lane == 31) warpsum[wid] = x;
    __syncthreads();
    if (wid == 0) {
        int s = warpsum[lane];
        #pragma unroll
        for (int d = 1; d < 32; d <<= 1) {
            int y = __shfl_up_sync(0xFFFFFFFFu, s, d);
            if (lane >= d) s += y;
        }
        warpsum[lane] = s;
    }
    __syncthreads();
    int incl = x + (wid > 0 ? warpsum[wid - 1] : 0);
    if (i < N_NODES) g_rowptr[i + 1] = incl;
    if (threadIdx.x == 1023) g_part[blockIdx.x] = incl;  // block total (OOB lanes contributed 0)
}

__global__ void k_scan2(int nb) {
    if (threadIdx.x == 0 && blockIdx.x == 0) {
        int run = 0;
        for (int b = 0; b < nb; b++) { int t = g_part[b]; g_part[b] = run; run += t; }
    }
}

__global__ void k_scan3() {
    int i = blockIdx.x * 1024 + threadIdx.x;
    if (i < N_NODES) g_rowptr[i + 1] += g_part[blockIdx.x];
    if (i == 0) g_rowptr[0] = 0;
}

__global__ void k_fill(const int* __restrict__ ei) {
    int e = blockIdx.x * blockDim.x + threadIdx.x;
    if (e < N_EDGES) {
        int src = ei[e];
        int dst = ei[N_EDGES + e];
        int pos = g_rowptr[dst] + atomicAdd(&g_cnt[dst], 1);
        g_col[pos] = src;
    }
}

// ---------------- SGEMM with fused dinv[row] scaling ----------------
// C[row, :] = (A[row, :] @ W) * dinv[row];  A: [M, KDIM], W: [KDIM, BN] row-major, BN == full N
template <int BN, int TN, int KDIM>
__device__ __forceinline__ void gemm_core(const float* __restrict__ A,
                                          const float* __restrict__ W,
                                          float* __restrict__ C, int M) {
    constexpr int BM = 128, BK = 16, TM = 8;
    constexpr int TX = BN / TN;  // 16
    __shared__ float As[BK][BM];
    __shared__ float Bs[BK][BN];
    int tid = threadIdx.x;  // 256
    int m0 = blockIdx.x * BM;
    int ty = tid / TX, tx = tid % TX;
    float acc[TM][TN];
    #pragma unroll
    for (int i = 0; i < TM; i++)
        #pragma unroll
        for (int j = 0; j < TN; j++) acc[i][j] = 0.f;

    for (int k0 = 0; k0 < KDIM; k0 += BK) {
        // A tile: BM x BK = 512 float4, 2 per thread (transposed store)
        #pragma unroll
        for (int l = 0; l < 2; l++) {
            int f = tid + l * 256;
            int row = f >> 2, c4 = f & 3;
            float4 v = make_float4(0.f, 0.f, 0.f, 0.f);
            if (m0 + row < M)
                v = *(const float4*)(A + (size_t)(m0 + row) * KDIM + k0 + c4 * 4);
            As[c4 * 4 + 0][row] = v.x;
            As[c4 * 4 + 1][row] = v.y;
            As[c4 * 4 + 2][row] = v.z;
            As[c4 * 4 + 3][row] = v.w;
        }
        // W tile: BK x BN
        constexpr int WF = BK * BN / 4;
        #pragma unroll
        for (int f = tid; f < WF; f += 256) {
            int row = f / (BN / 4), c = f % (BN / 4);
            float4 v = *(const float4*)(W + (size_t)(k0 + row) * BN + c * 4);
            *(float4*)&Bs[row][c * 4] = v;
        }
        __syncthreads();
        #pragma unroll
        for (int k = 0; k < BK; k++) {
            float ra[TM], rb[TN];
            #pragma unroll
            for (int i = 0; i < TM; i++) ra[i] = As[k][ty * TM + i];
            #pragma unroll
            for (int j = 0; j < TN; j++) rb[j] = Bs[k][tx * TN + j];
            #pragma unroll
            for (int i = 0; i < TM; i++)
                #pragma unroll
                for (int j = 0; j < TN; j++) acc[i][j] += ra[i] * rb[j];
        }
        __syncthreads();
    }
    #pragma unroll
    for (int i = 0; i < TM; i++) {
        int row = m0 + ty * TM + i;
        if (row < M) {
            float d = g_dinv[row];
            #pragma unroll
            for (int j = 0; j < TN; j++)
                C[(size_t)row * BN + tx * TN + j] = acc[i][j] * d;
        }
    }
}

__global__ void k_gemm1(const float* __restrict__ x, const float* __restrict__ W1) {
    gemm_core<HID, 8, IN_CH>(x, W1, g_xw, N_NODES);
}
__global__ void k_gemm2(const float* __restrict__ W2) {
    gemm_core<OUT_CH, 4, HID>(g_h, W2, g_hw, N_NODES);
}

// ---------------- warp-per-node aggregation ----------------
// out[v] = act( dinv[v] * ( in[v] + sum_{s in N(v)} in[s] ) + bias )
template <int CH, bool RELU>
__device__ __forceinline__ void agg_core(const float* __restrict__ in,
                                         const float* __restrict__ bias,
                                         float* __restrict__ out) {
    int w = (int)((blockIdx.x * (size_t)blockDim.x + threadIdx.x) >> 5);
    if (w >= N_NODES) return;
    int lane = threadIdx.x & 31;
    constexpr int V = CH / 32;  // 4 or 2 floats per lane

    float acc[V];
    {
        const float* p = in + (size_t)w * CH + lane * V;
        if (V == 4) { float4 v = *(const float4*)p; acc[0]=v.x; acc[1]=v.y; acc[2]=v.z; acc[3]=v.w; }
        else        { float2 v = *(const float2*)p; acc[0]=v.x; acc[1]=v.y; }
    }
    int s = g_rowptr[w], e = g_rowptr[w + 1];
    for (int i = s; i < e; i++) {
        int src = g_col[i];
        const float* p = in + (size_t)src * CH + lane * V;
        if (V == 4) { float4 v = *(const float4*)p; acc[0]+=v.x; acc[1]+=v.y; acc[2]+=v.z; acc[3]+=v.w; }
        else        { float2 v = *(const float2*)p; acc[0]+=v.x; acc[1]+=v.y; }
    }
    float d = g_dinv[w];
    #pragma unroll
    for (int c = 0; c < V; c++) {
        float r = acc[c] * d + __ldg(bias + lane * V + c);
        if (RELU) r = fmaxf(r, 0.f);
        acc[c] = r;
    }
    float* q = out + (size_t)w * CH + lane * V;
    if (V == 4) *(float4*)q = make_float4(acc[0], acc[1], acc[2], acc[3]);
    else        *(float2*)q = make_float2(acc[0], acc[1]);
}

__global__ void k_agg1(const float* __restrict__ b1) { agg_core<HID, true>(g_xw, b1, g_h); }
__global__ void k_agg2(const float* __restrict__ b2, float* __restrict__ out) {
    agg_core<OUT_CH, false>(g_hw, b2, out);
}

// ---------------- launch ----------------
extern "C" void kernel_launch(void* const* d_in, const int* in_sizes, int n_in,
                              void* d_out, int out_size) {
    const float* x  = (const float*)d_in[0];
    const int*   ei = (const int*)d_in[1];   // JAX w/o x64: int64 request -> int32 array
    const float* W1 = (const float*)d_in[2];
    const float* b1 = (const float*)d_in[3];
    const float* W2 = (const float*)d_in[4];
    const float* b2 = (const float*)d_in[5];
    float* out = (float*)d_out;

    const int nbScan = (N_NODES + 1023) / 1024;  // 98

    k_zero_cnt<<<(N_NODES + 255) / 256, 256>>>();
    k_hist<<<(N_EDGES + 255) / 256, 256>>>(ei);
    k_dinv<<<(N_NODES + 255) / 256, 256>>>();
    k_scan1<<<nbScan, 1024>>>();
    k_scan2<<<1, 32>>>(nbScan);
    k_scan3<<<nbScan, 1024>>>();
    k_zero_cnt<<<(N_NODES + 255) / 256, 256>>>();
    k_fill<<<(N_EDGES + 255) / 256, 256>>>(ei);

    k_gemm1<<<(N_NODES + 127) / 128, 256>>>(x, W1);
    k_agg1<<<(N_NODES * 32 + 255) / 256, 256>>>(b1);
    k_gemm2<<<(N_NODES + 127) / 128, 256>>>(W2);
    k_agg2<<<(N_NODES * 32 + 255) / 256, 256>>>(b2, out);
}

// round 4
// speedup vs baseline: 1.6809x; 1.6809x over previous
#include <cuda_runtime.h>
#include <cstdint>
#include <cstddef>

#define N_NODES 100000
#define N_EDGES 1600000
#define IN_CH   256
#define HID     128
#define OUT_CH  64

// ---------------- scratch (no allocs allowed) ----------------
__device__ int   g_cnt[N_NODES];
__device__ int   g_rowptr[N_NODES + 1];
__device__ int   g_part[128];
__device__ int   g_col[N_EDGES];
__device__ float g_dinv[N_NODES];
__device__ float g_wt1[HID * IN_CH];              // W1^T, tf32-rounded
__device__ float g_wt2[OUT_CH * HID];             // W2^T, tf32-rounded
__device__ float g_xw[(size_t)N_NODES * HID];     // x @ W1 (unscaled)
__device__ float g_h [(size_t)N_NODES * HID];     // relu(layer1)
__device__ float g_hw[(size_t)N_NODES * OUT_CH];  // h @ W2 (unscaled)

// ---------------- small PTX helpers ----------------
__device__ __forceinline__ uint32_t smem_u32(const void* p) {
    return (uint32_t)__cvta_generic_to_shared(p);
}
__device__ __forceinline__ void cp16(uint32_t dst, const void* src, bool pred) {
    asm volatile("cp.async.cg.shared.global [%0], [%1], 16, %2;"
                 :: "r"(dst), "l"(src), "r"(pred ? 16 : 0));
}
__device__ __forceinline__ void cp_commit() { asm volatile("cp.async.commit_group;"); }
template <int N>
__device__ __forceinline__ void cp_wait() { asm volatile("cp.async.wait_group %0;" :: "n"(N)); }

__device__ __forceinline__ void ldsm4(uint32_t& r0, uint32_t& r1, uint32_t& r2, uint32_t& r3,
                                      uint32_t addr) {
    asm volatile("ldmatrix.sync.aligned.m8n8.x4.b16 {%0,%1,%2,%3}, [%4];"
                 : "=r"(r0), "=r"(r1), "=r"(r2), "=r"(r3) : "r"(addr));
}
__device__ __forceinline__ void mma_tf32(float* c, const uint32_t* a, const uint32_t* b) {
    asm volatile("mma.sync.aligned.m16n8k8.row.col.f32.tf32.tf32.f32 "
                 "{%0,%1,%2,%3}, {%4,%5,%6,%7}, {%8,%9}, {%0,%1,%2,%3};"
                 : "+f"(c[0]), "+f"(c[1]), "+f"(c[2]), "+f"(c[3])
                 : "r"(a[0]), "r"(a[1]), "r"(a[2]), "r"(a[3]), "r"(b[0]), "r"(b[1]));
}
__device__ __forceinline__ uint32_t to_tf32(uint32_t x) {
    float f = __uint_as_float(x);
    uint32_t o;
    asm("cvt.rna.tf32.f32 %0, %1;" : "=r"(o) : "f"(f));
    return o;
}
__device__ __forceinline__ float round_tf32_f(float f) {
    uint32_t o;
    asm("cvt.rna.tf32.f32 %0, %1;" : "=r"(o) : "f"(f));
    return __uint_as_float(o);
}

// ---------------- prep: zero cnt + transpose/round weights ----------------
__global__ void k_prep(const float* __restrict__ W1, const float* __restrict__ W2) {
    int i = blockIdx.x * blockDim.x + threadIdx.x;
    if (i < N_NODES) g_cnt[i] = 0;
    if (i < IN_CH * HID) {             // W1 [256][128] -> Wt1 [128][256]
        int k = i / HID, n = i % HID;
        g_wt1[n * IN_CH + k] = round_tf32_f(W1[i]);
    }
    if (i < HID * OUT_CH) {            // W2 [128][64] -> Wt2 [64][128]
        int k = i / OUT_CH, n = i % OUT_CH;
        g_wt2[n * HID + k] = round_tf32_f(W2[i]);
    }
}

// ---------------- degree / CSR build ----------------
__global__ void k_hist(const int* __restrict__ ei) {
    int e = blockIdx.x * blockDim.x + threadIdx.x;
    if (e < N_EDGES) atomicAdd(&g_cnt[ei[N_EDGES + e]], 1);
}

__global__ void k_scan1() {
    __shared__ int warpsum[32];
    int i = blockIdx.x * 1024 + threadIdx.x;
    int lane = threadIdx.x & 31, wid = threadIdx.x >> 5;
    int c = (i < N_NODES) ? g_cnt[i] : 0;
    if (i < N_NODES) g_dinv[i] = rsqrtf((float)c + 1.0f);  // +1 self loop
    int x = c;
    #pragma unroll
    for (int d = 1; d < 32; d <<= 1) {
        int y = __shfl_up_sync(0xFFFFFFFFu, x, d);
        if (lane >= d) x += y;
    }
    if (lane == 31) warpsum[wid] = x;
    __syncthreads();
    if (wid == 0) {
        int s = warpsum[lane];
        #pragma unroll
        for (int d = 1; d < 32; d <<= 1) {
            int y = __shfl_up_sync(0xFFFFFFFFu, s, d);
            if (lane >= d) s += y;
        }
        warpsum[lane] = s;
    }
    __syncthreads();
    int incl = x + (wid > 0 ? warpsum[wid - 1] : 0);
    if (i < N_NODES) g_rowptr[i + 1] = incl;
    if (threadIdx.x == 1023) g_part[blockIdx.x] = incl;
}

__global__ void k_scan2(int nb) {  // one block of 128, scan partials
    __shared__ int warpsum[4];
    int i = threadIdx.x;
    int lane = i & 31, wid = i >> 5;
    int v = (i < nb) ? g_part[i] : 0;
    int x = v;
    #pragma unroll
    for (int d = 1; d < 32; d <<= 1) {
        int y = __shfl_up_sync(0xFFFFFFFFu, x, d);
        if (lane >= d) x += y;
    }
    if (lane == 31) warpsum[wid] = x;
    __syncthreads();
    int base = 0;
    #pragma unroll
    for (int w = 0; w < 4; w++) if (w < wid) base += warpsum[w];
    if (i < nb) g_part[i] = base + x - v;  // exclusive
}

__global__ void k_scan3() {
    int i = blockIdx.x * 1024 + threadIdx.x;
    if (i < N_NODES) {
        g_rowptr[i + 1] += g_part[blockIdx.x];
        g_cnt[i] = 0;  // reset for fill
    }
    if (i == 0) g_rowptr[0] = 0;
}

__global__ void k_fill(const int* __restrict__ ei) {
    int e = blockIdx.x * blockDim.x + threadIdx.x;
    if (e < N_EDGES) {
        int src = ei[e];
        int dst = ei[N_EDGES + e];
        int pos = g_rowptr[dst] + atomicAdd(&g_cnt[dst], 1);
        g_col[pos] = src;
    }
}

// ---------------- tf32 tensor-core GEMM: C[M,BN] = A[M,KDIM] @ Wt^T ----------------
// Wt is [BN][KDIM] (pre-transposed, tf32-rounded). 256 threads, BM=128, BK=16.
template <int BN, int KDIM>
__global__ void __launch_bounds__(256) k_gemm(const float* __restrict__ A,
                                              const float* __restrict__ Wt,
                                              float* __restrict__ C, int M) {
    constexpr int BM = 128, BK = 16;
    constexpr int NK = KDIM / BK;
    constexpr int LDSW = 20;             // 16 + 4 pad -> conflict-free ldmatrix
    constexpr int N_TILES = BN / 16;     // n8 tiles per warp (warp covers BN/2)
    __shared__ float As[2][BM][LDSW];
    __shared__ float Bs[2][BN][LDSW];

    const int tid = threadIdx.x;
    const int lane = tid & 31, wid = tid >> 5;
    const int wm = (wid & 3) * 32;               // warp m-origin (2 x m16)
    const int wn = (wid >> 2) * (BN / 2);        // warp n-origin
    const int m0 = blockIdx.x * BM;

    float acc[2][N_TILES][4];
    #pragma unroll
    for (int mt = 0; mt < 2; mt++)
        #pragma unroll
        for (int nt = 0; nt < N_TILES; nt++)
            #pragma unroll
            for (int r = 0; r < 4; r++) acc[mt][nt][r] = 0.f;

    // ---- tile loader (cp.async) ----
    #define LOAD_TILE(T, BUF)                                                        \
    {                                                                                \
        const int k0_ = (T) * BK;                                                    \
        _Pragma("unroll")                                                            \
        for (int l = 0; l < 2; l++) {                                                \
            int q = tid + l * 256;                                                   \
            int row = q >> 2, kq = q & 3;                                            \
            cp16(smem_u32(&As[BUF][row][kq * 4]),                                    \
                 A + (size_t)(m0 + row) * KDIM + k0_ + kq * 4, (m0 + row) < M);      \
        }                                                                            \
        _Pragma("unroll")                                                            \
        for (int l = 0; l < BN / 64; l++) {                                          \
            int q = tid + l * 256;                                                   \
            int n = q >> 2, kq = q & 3;                                              \
            cp16(smem_u32(&Bs[BUF][n][kq * 4]),                                      \
                 Wt + (size_t)n * KDIM + k0_ + kq * 4, true);                        \
        }                                                                            \
        cp_commit();                                                                 \
    }

    LOAD_TILE(0, 0);
    int buf = 0;
    for (int t = 0; t < NK; t++) {
        if (t + 1 < NK) { LOAD_TILE(t + 1, buf ^ 1); cp_wait<1>(); }
        else            { cp_wait<0>(); }
        __syncthreads();

        #pragma unroll
        for (int ks = 0; ks < 2; ks++) {
            const int kb = ks * 8;
            uint32_t a[2][4];
            #pragma unroll
            for (int mt = 0; mt < 2; mt++) {
                int row = wm + mt * 16 + (lane & 15);
                int col = kb + ((lane & 16) >> 2);
                ldsm4(a[mt][0], a[mt][1], a[mt][2], a[mt][3],
                      smem_u32(&As[buf][row][col]));
                #pragma unroll
                for (int r = 0; r < 4; r++) a[mt][r] = to_tf32(a[mt][r]);
            }
            uint32_t b[N_TILES][2];
            #pragma unroll
            for (int np = 0; np < N_TILES / 2; np++) {
                int row = wn + np * 16 + (lane & 7) + ((lane & 16) >> 1);
                int col = kb + ((lane & 8) >> 1);
                uint32_t r0, r1, r2, r3;
                ldsm4(r0, r1, r2, r3, smem_u32(&Bs[buf][row][col]));
                b[2 * np][0] = r0; b[2 * np][1] = r1;
                b[2 * np + 1][0] = r2; b[2 * np + 1][1] = r3;
            }
            #pragma unroll
            for (int mt = 0; mt < 2; mt++)
                #pragma unroll
                for (int nt = 0; nt < N_TILES; nt++)
                    mma_tf32(acc[mt][nt], a[mt], b[nt]);
        }
        __syncthreads();
        buf ^= 1;
    }
    #undef LOAD_TILE

    // epilogue
    #pragma unroll
    for (int mt = 0; mt < 2; mt++) {
        int r0 = m0 + wm + mt * 16 + (lane >> 2);
        #pragma unroll
        for (int nt = 0; nt < N_TILES; nt++) {
            int cix = wn + nt * 8 + (lane & 3) * 2;
            if (r0 < M)
                *(float2*)&C[(size_t)r0 * BN + cix] = make_float2(acc[mt][nt][0], acc[mt][nt][1]);
            if (r0 + 8 < M)
                *(float2*)&C[(size_t)(r0 + 8) * BN + cix] = make_float2(acc[mt][nt][2], acc[mt][nt][3]);
        }
    }
}

// ---------------- warp-per-node aggregation ----------------
// out[v] = act( dinv[v] * ( dinv[v]*in[v] + sum_{s in N(v)} dinv[s]*in[s] ) + bias )
template <int CH, bool RELU>
__device__ __forceinline__ void agg_core(const float* __restrict__ in,
                                         const float* __restrict__ bias,
                                         float* __restrict__ out) {
    int w = (int)((blockIdx.x * (size_t)blockDim.x + threadIdx.x) >> 5);
    if (w >= N_NODES) return;
    int lane = threadIdx.x & 31;
    constexpr int V = CH / 32;  // 4 (CH=128) or 2 (CH=64)

    float dv = g_dinv[w];
    float acc[V];
    {
        // self term: contributes dv*dv overall; we multiply by dv at the end,
        // so seed with in[v]*dv (NOT dv^2 -- that was the R3 bug).
        const float* p = in + (size_t)w * CH + lane * V;
        if (V == 4) { float4 v = *(const float4*)p;
                      acc[0]=v.x*dv; acc[1]=v.y*dv; acc[2]=v.z*dv; acc[3]=v.w*dv; }
        else        { float2 v = *(const float2*)p; acc[0]=v.x*dv; acc[1]=v.y*dv; }
    }
    int s = g_rowptr[w], e = g_rowptr[w + 1];
    int i = s;
    int e4 = s + ((e - s) & ~3);
    for (; i < e4; i += 4) {
        int c0 = __ldg(&g_col[i]),     c1 = __ldg(&g_col[i + 1]);
        int c2 = __ldg(&g_col[i + 2]), c3 = __ldg(&g_col[i + 3]);
        float d0 = __ldg(&g_dinv[c0]), d1 = __ldg(&g_dinv[c1]);
        float d2 = __ldg(&g_dinv[c2]), d3 = __ldg(&g_dinv[c3]);
        if (V == 4) {
            float4 v0 = *(const float4*)(in + (size_t)c0 * CH + lane * 4);
            float4 v1 = *(const float4*)(in + (size_t)c1 * CH + lane * 4);
            float4 v2 = *(const float4*)(in + (size_t)c2 * CH + lane * 4);
            float4 v3 = *(const float4*)(in + (size_t)c3 * CH + lane * 4);
            acc[0] += v0.x*d0 + v1.x*d1 + v2.x*d2 + v3.x*d3;
            acc[1] += v0.y*d0 + v1.y*d1 + v2.y*d2 + v3.y*d3;
            acc[2] += v0.z*d0 + v1.z*d1 + v2.z*d2 + v3.z*d3;
            acc[3] += v0.w*d0 + v1.w*d1 + v2.w*d2 + v3.w*d3;
        } else {
            float2 v0 = *(const float2*)(in + (size_t)c0 * CH + lane * 2);
            float2 v1 = *(const float2*)(in + (size_t)c1 * CH + lane * 2);
            float2 v2 = *(const float2*)(in + (size_t)c2 * CH + lane * 2);
            float2 v3 = *(const float2*)(in + (size_t)c3 * CH + lane * 2);
            acc[0] += v0.x*d0 + v1.x*d1 + v2.x*d2 + v3.x*d3;
            acc[1] += v0.y*d0 + v1.y*d1 + v2.y*d2 + v3.y*d3;
        }
    }
    for (; i < e; i++) {
        int c = __ldg(&g_col[i]);
        float d = __ldg(&g_dinv[c]);
        const float* p = in + (size_t)c * CH + lane * V;
        if (V == 4) { float4 v = *(const float4*)p;
                      acc[0]+=v.x*d; acc[1]+=v.y*d; acc[2]+=v.z*d; acc[3]+=v.w*d; }
        else        { float2 v = *(const float2*)p; acc[0]+=v.x*d; acc[1]+=v.y*d; }
    }
    #pragma unroll
    for (int c = 0; c < V; c++) {
        float r = acc[c] * dv + __ldg(bias + lane * V + c);
        if (RELU) r = fmaxf(r, 0.f);
        acc[c] = r;
    }
    float* q = out + (size_t)w * CH + lane * V;
    if (V == 4) *(float4*)q = make_float4(acc[0], acc[1], acc[2], acc[3]);
    else        *(float2*)q = make_float2(acc[0], acc[1]);
}

__global__ void k_agg1(const float* __restrict__ b1) { agg_core<HID, true>(g_xw, b1, g_h); }
__global__ void k_agg2(const float* __restrict__ b2, float* __restrict__ out) {
    agg_core<OUT_CH, false>(g_hw, b2, out);
}

// ---------------- launch ----------------
extern "C" void kernel_launch(void* const* d_in, const int* in_sizes, int n_in,
                              void* d_out, int out_size) {
    const float* x  = (const float*)d_in[0];
    const int*   ei = (const int*)d_in[1];
    const float* W1 = (const float*)d_in[2];
    const float* b1 = (const float*)d_in[3];
    const float* W2 = (const float*)d_in[4];
    const float* b2 = (const float*)d_in[5];
    float* out = (float*)d_out;

    float* xw = nullptr; float* h = nullptr; float* hw = nullptr;
    cudaGetSymbolAddress((void**)&xw, g_xw);
    cudaGetSymbolAddress((void**)&h,  g_h);
    cudaGetSymbolAddress((void**)&hw, g_hw);
    float* wt1 = nullptr; float* wt2 = nullptr;
    cudaGetSymbolAddress((void**)&wt1, g_wt1);
    cudaGetSymbolAddress((void**)&wt2, g_wt2);

    const int nbScan = (N_NODES + 1023) / 1024;  // 98

    k_prep<<<(N_NODES + 255) / 256, 256>>>(W1, W2);
    k_hist<<<(N_EDGES + 255) / 256, 256>>>(ei);
    k_scan1<<<nbScan, 1024>>>();
    k_scan2<<<1, 128>>>(nbScan);
    k_scan3<<<nbScan, 1024>>>();
    k_fill<<<(N_EDGES + 255) / 256, 256>>>(ei);

    k_gemm<HID, IN_CH><<<(N_NODES + 127) / 128, 256>>>(x, wt1, xw, N_NODES);
    k_agg1<<<(N_NODES * 32 + 255) / 256, 256>>>(b1);
    k_gemm<OUT_CH, HID><<<(N_NODES + 127) / 128, 256>>>(h, wt2, hw, N_NODES);
    k_agg2<<<(N_NODES * 32 + 255) / 256, 256>>>(b2, out);
}

// round 5
// speedup vs baseline: 1.7879x; 1.0636x over previous
#include <cuda_runtime.h>
#include <cstdint>
#include <cstddef>

#define N_NODES 100000
#define N_EDGES 1600000
#define IN_CH   256
#define HID     128
#define OUT_CH  64
#define NB_SCAN ((N_NODES + 1023) / 1024)   // 98

// ---------------- scratch (no allocs allowed) ----------------
__device__ int   g_cnt[N_NODES];            // zero at load; re-zeroed by agg2 tail each call
__device__ int   g_rowptr[N_NODES + 1];
__device__ int   g_part[128];
__device__ int   g_col[N_EDGES];
__device__ float g_dinv[N_NODES];
__device__ float g_wt1[HID * IN_CH];        // W1^T, tf32-rounded
__device__ float g_wt2[OUT_CH * HID];       // W2^T, tf32-rounded
__device__ float g_xw[(size_t)N_NODES * HID];
__device__ float g_h [(size_t)N_NODES * HID];
__device__ float g_hw[(size_t)N_NODES * OUT_CH];

// ---------------- small PTX helpers ----------------
__device__ __forceinline__ uint32_t smem_u32(const void* p) {
    return (uint32_t)__cvta_generic_to_shared(p);
}
__device__ __forceinline__ void cp16(uint32_t dst, const void* src, bool pred) {
    asm volatile("cp.async.cg.shared.global [%0], [%1], 16, %2;"
                 :: "r"(dst), "l"(src), "r"(pred ? 16 : 0));
}
__device__ __forceinline__ void cp_commit() { asm volatile("cp.async.commit_group;"); }
template <int N>
__device__ __forceinline__ void cp_wait() { asm volatile("cp.async.wait_group %0;" :: "n"(N)); }

__device__ __forceinline__ void ldsm4(uint32_t& r0, uint32_t& r1, uint32_t& r2, uint32_t& r3,
                                      uint32_t addr) {
    asm volatile("ldmatrix.sync.aligned.m8n8.x4.b16 {%0,%1,%2,%3}, [%4];"
                 : "=r"(r0), "=r"(r1), "=r"(r2), "=r"(r3) : "r"(addr));
}
__device__ __forceinline__ void mma_tf32(float* c, const uint32_t* a, const uint32_t* b) {
    asm volatile("mma.sync.aligned.m16n8k8.row.col.f32.tf32.tf32.f32 "
                 "{%0,%1,%2,%3}, {%4,%5,%6,%7}, {%8,%9}, {%0,%1,%2,%3};"
                 : "+f"(c[0]), "+f"(c[1]), "+f"(c[2]), "+f"(c[3])
                 : "r"(a[0]), "r"(a[1]), "r"(a[2]), "r"(a[3]), "r"(b[0]), "r"(b[1]));
}
__device__ __forceinline__ uint32_t to_tf32(uint32_t x) {
    float f = __uint_as_float(x);
    uint32_t o;
    asm("cvt.rna.tf32.f32 %0, %1;" : "=r"(o) : "f"(f));
    return o;
}
__device__ __forceinline__ float round_tf32_f(float f) {
    uint32_t o;
    asm("cvt.rna.tf32.f32 %0, %1;" : "=r"(o) : "f"(f));
    return __uint_as_float(o);
}

// ---------------- weight transpose/round (gemm-stream) ----------------
__global__ void k_prep_w(const float* __restrict__ W1, const float* __restrict__ W2) {
    int i = blockIdx.x * blockDim.x + threadIdx.x;
    if (i < IN_CH * HID) {             // W1 [256][128] -> Wt1 [128][256]
        int k = i / HID, n = i % HID;
        g_wt1[n * IN_CH + k] = round_tf32_f(W1[i]);
    }
    if (i < HID * OUT_CH) {            // W2 [128][64] -> Wt2 [64][128]
        int k = i / OUT_CH, n = i % OUT_CH;
        g_wt2[n * HID + k] = round_tf32_f(W2[i]);
    }
}

// ---------------- degree / CSR build (graph-stream) ----------------
__global__ void k_hist(const int* __restrict__ ei) {
    int e = blockIdx.x * blockDim.x + threadIdx.x;
    if (e < N_EDGES) atomicAdd(&g_cnt[ei[N_EDGES + e]], 1);
}

__global__ void k_scan1() {
    __shared__ int warpsum[32];
    int i = blockIdx.x * 1024 + threadIdx.x;
    int lane = threadIdx.x & 31, wid = threadIdx.x >> 5;
    int c = (i < N_NODES) ? g_cnt[i] : 0;
    if (i < N_NODES) g_dinv[i] = rsqrtf((float)c + 1.0f);  // +1 self loop
    int x = c;
    #pragma unroll
    for (int d = 1; d < 32; d <<= 1) {
        int y = __shfl_up_sync(0xFFFFFFFFu, x, d);
        if (lane >= d) x += y;
    }
    if (lane == 31) warpsum[wid] = x;
    __syncthreads();
    if (wid == 0) {
        int s = warpsum[lane];
        #pragma unroll
        for (int d = 1; d < 32; d <<= 1) {
            int y = __shfl_up_sync(0xFFFFFFFFu, s, d);
            if (lane >= d) s += y;
        }
        warpsum[lane] = s;
    }
    __syncthreads();
    int incl = x + (wid > 0 ? warpsum[wid - 1] : 0);
    if (i < N_NODES) g_rowptr[i + 1] = incl;
    if (threadIdx.x == 1023) g_part[blockIdx.x] = incl;
}

// fused scan2+scan3: every block redundantly scans the 98 partials in smem
__global__ void k_scan23() {
    __shared__ int parts[128];
    int tid = threadIdx.x;
    if (tid < 128) parts[tid] = (tid < NB_SCAN) ? g_part[tid] : 0;
    __syncthreads();
    #pragma unroll
    for (int d = 1; d < 128; d <<= 1) {
        int t = (tid < 128 && tid >= d) ? parts[tid - d] : 0;
        __syncthreads();
        if (tid < 128) parts[tid] += t;
        __syncthreads();
    }
    int base = (blockIdx.x > 0) ? parts[blockIdx.x - 1] : 0;  // exclusive prefix
    int i = blockIdx.x * 1024 + tid;
    if (i < N_NODES) {
        g_rowptr[i + 1] += base;
        g_cnt[i] = 0;  // reset for fill
    }
    if (i == 0) g_rowptr[0] = 0;
}

__global__ void k_fill(const int* __restrict__ ei) {
    int e = blockIdx.x * blockDim.x + threadIdx.x;
    if (e < N_EDGES) {
        int src = ei[e];
        int dst = ei[N_EDGES + e];
        int pos = g_rowptr[dst] + atomicAdd(&g_cnt[dst], 1);
        g_col[pos] = src;
    }
}

// ---------------- tf32 tensor-core GEMM: C[M,BN] = A[M,KDIM] @ Wt^T ----------------
template <int BN, int KDIM>
__global__ void __launch_bounds__(256) k_gemm(const float* __restrict__ A,
                                              const float* __restrict__ Wt,
                                              float* __restrict__ C, int M) {
    constexpr int BM = 128, BK = 16;
    constexpr int NK = KDIM / BK;
    constexpr int LDSW = 20;             // 16 + 4 pad -> conflict-free ldmatrix
    constexpr int N_TILES = BN / 16;
    __shared__ float As[2][BM][LDSW];
    __shared__ float Bs[2][BN][LDSW];

    const int tid = threadIdx.x;
    const int lane = tid & 31, wid = tid >> 5;
    const int wm = (wid & 3) * 32;
    const int wn = (wid >> 2) * (BN / 2);
    const int m0 = blockIdx.x * BM;

    float acc[2][N_TILES][4];
    #pragma unroll
    for (int mt = 0; mt < 2; mt++)
        #pragma unroll
        for (int nt = 0; nt < N_TILES; nt++)
            #pragma unroll
            for (int r = 0; r < 4; r++) acc[mt][nt][r] = 0.f;

    #define LOAD_TILE(T, BUF)                                                        \
    {                                                                                \
        const int k0_ = (T) * BK;                                                    \
        _Pragma("unroll")                                                            \
        for (int l = 0; l < 2; l++) {                                                \
            int q = tid + l * 256;                                                   \
            int row = q >> 2, kq = q & 3;                                            \
            cp16(smem_u32(&As[BUF][row][kq * 4]),                                    \
                 A + (size_t)(m0 + row) * KDIM + k0_ + kq * 4, (m0 + row) < M);      \
        }                                                                            \
        _Pragma("unroll")                                                            \
        for (int l = 0; l < BN / 64; l++) {                                          \
            int q = tid + l * 256;                                                   \
            int n = q >> 2, kq = q & 3;                                              \
            cp16(smem_u32(&Bs[BUF][n][kq * 4]),                                      \
                 Wt + (size_t)n * KDIM + k0_ + kq * 4, true);                        \
        }                                                                            \
        cp_commit();                                                                 \
    }

    LOAD_TILE(0, 0);
    int buf = 0;
    for (int t = 0; t < NK; t++) {
        if (t + 1 < NK) { LOAD_TILE(t + 1, buf ^ 1); cp_wait<1>(); }
        else            { cp_wait<0>(); }
        __syncthreads();

        #pragma unroll
        for (int ks = 0; ks < 2; ks++) {
            const int kb = ks * 8;
            uint32_t a[2][4];
            #pragma unroll
            for (int mt = 0; mt < 2; mt++) {
                int row = wm + mt * 16 + (lane & 15);
                int col = kb + ((lane & 16) >> 2);
                ldsm4(a[mt][0], a[mt][1], a[mt][2], a[mt][3],
                      smem_u32(&As[buf][row][col]));
                #pragma unroll
                for (int r = 0; r < 4; r++) a[mt][r] = to_tf32(a[mt][r]);
            }
            uint32_t b[N_TILES][2];
            #pragma unroll
            for (int np = 0; np < N_TILES / 2; np++) {
                int row = wn + np * 16 + (lane & 7) + ((lane & 16) >> 1);
                int col = kb + ((lane & 8) >> 1);
                uint32_t r0, r1, r2, r3;
                ldsm4(r0, r1, r2, r3, smem_u32(&Bs[buf][row][col]));
                b[2 * np][0] = r0; b[2 * np][1] = r1;
                b[2 * np + 1][0] = r2; b[2 * np + 1][1] = r3;
            }
            #pragma unroll
            for (int mt = 0; mt < 2; mt++)
                #pragma unroll
                for (int nt = 0; nt < N_TILES; nt++)
                    mma_tf32(acc[mt][nt], a[mt], b[nt]);
        }
        __syncthreads();
        buf ^= 1;
    }
    #undef LOAD_TILE

    #pragma unroll
    for (int mt = 0; mt < 2; mt++) {
        int r0 = m0 + wm + mt * 16 + (lane >> 2);
        #pragma unroll
        for (int nt = 0; nt < N_TILES; nt++) {
            int cix = wn + nt * 8 + (lane & 3) * 2;
            if (r0 < M)
                *(float2*)&C[(size_t)r0 * BN + cix] = make_float2(acc[mt][nt][0], acc[mt][nt][1]);
            if (r0 + 8 < M)
                *(float2*)&C[(size_t)(r0 + 8) * BN + cix] = make_float2(acc[mt][nt][2], acc[mt][nt][3]);
        }
    }
}

// ---------------- warp-per-node aggregation ----------------
// out[v] = act( dinv[v] * ( dinv[v]*in[v] + sum_s dinv[s]*in[s] ) + bias )
template <int CH, bool RELU, bool ZERO_CNT>
__device__ __forceinline__ void agg_core(const float* __restrict__ in,
                                         const float* __restrict__ bias,
                                         float* __restrict__ out) {
    int w = (int)((blockIdx.x * (size_t)blockDim.x + threadIdx.x) >> 5);
    if (w >= N_NODES) return;
    int lane = threadIdx.x & 31;
    constexpr int V = CH / 32;

    if (ZERO_CNT && lane == 0) g_cnt[w] = 0;  // restore invariant for next call

    float dv = g_dinv[w];
    float acc[V];
    {
        const float* p = in + (size_t)w * CH + lane * V;
        if (V == 4) { float4 v = *(const float4*)p;
                      acc[0]=v.x*dv; acc[1]=v.y*dv; acc[2]=v.z*dv; acc[3]=v.w*dv; }
        else        { float2 v = *(const float2*)p; acc[0]=v.x*dv; acc[1]=v.y*dv; }
    }
    int s = g_rowptr[w], e = g_rowptr[w + 1];
    int i = s;
    int e4 = s + ((e - s) & ~3);
    for (; i < e4; i += 4) {
        int c0 = __ldg(&g_col[i]),     c1 = __ldg(&g_col[i + 1]);
        int c2 = __ldg(&g_col[i + 2]), c3 = __ldg(&g_col[i + 3]);
        float d0 = __ldg(&g_dinv[c0]), d1 = __ldg(&g_dinv[c1]);
        float d2 = __ldg(&g_dinv[c2]), d3 = __ldg(&g_dinv[c3]);
        if (V == 4) {
            float4 v0 = *(const float4*)(in + (size_t)c0 * CH + lane * 4);
            float4 v1 = *(const float4*)(in + (size_t)c1 * CH + lane * 4);
            float4 v2 = *(const float4*)(in + (size_t)c2 * CH + lane * 4);
            float4 v3 = *(const float4*)(in + (size_t)c3 * CH + lane * 4);
            acc[0] += v0.x*d0 + v1.x*d1 + v2.x*d2 + v3.x*d3;
            acc[1] += v0.y*d0 + v1.y*d1 + v2.y*d2 + v3.y*d3;
            acc[2] += v0.z*d0 + v1.z*d1 + v2.z*d2 + v3.z*d3;
            acc[3] += v0.w*d0 + v1.w*d1 + v2.w*d2 + v3.w*d3;
        } else {
            float2 v0 = *(const float2*)(in + (size_t)c0 * CH + lane * 2);
            float2 v1 = *(const float2*)(in + (size_t)c1 * CH + lane * 2);
            float2 v2 = *(const float2*)(in + (size_t)c2 * CH + lane * 2);
            float2 v3 = *(const float2*)(in + (size_t)c3 * CH + lane * 2);
            acc[0] += v0.x*d0 + v1.x*d1 + v2.x*d2 + v3.x*d3;
            acc[1] += v0.y*d0 + v1.y*d1 + v2.y*d2 + v3.y*d3;
        }
    }
    for (; i < e; i++) {
        int c = __ldg(&g_col[i]);
        float d = __ldg(&g_dinv[c]);
        const float* p = in + (size_t)c * CH + lane * V;
        if (V == 4) { float4 v = *(const float4*)p;
                      acc[0]+=v.x*d; acc[1]+=v.y*d; acc[2]+=v.z*d; acc[3]+=v.w*d; }
        else        { float2 v = *(const float2*)p; acc[0]+=v.x*d; acc[1]+=v.y*d; }
    }
    #pragma unroll
    for (int c = 0; c < V; c++) {
        float r = acc[c] * dv + __ldg(bias + lane * V + c);
        if (RELU) r = fmaxf(r, 0.f);
        acc[c] = r;
    }
    float* q = out + (size_t)w * CH + lane * V;
    if (V == 4) *(float4*)q = make_float4(acc[0], acc[1], acc[2], acc[3]);
    else        *(float2*)q = make_float2(acc[0], acc[1]);
}

__global__ void k_agg1(const float* __restrict__ b1) { agg_core<HID, true, false>(g_xw, b1, g_h); }
__global__ void k_agg2(const float* __restrict__ b2, float* __restrict__ out) {
    agg_core<OUT_CH, false, true>(g_hw, b2, out);
}

// ---------------- launch (forked capture: CSR chain || prep+gemm1) ----------------
extern "C" void kernel_launch(void* const* d_in, const int* in_sizes, int n_in,
                              void* d_out, int out_size) {
    const float* x  = (const float*)d_in[0];
    const int*   ei = (const int*)d_in[1];
    const float* W1 = (const float*)d_in[2];
    const float* b1 = (const float*)d_in[3];
    const float* W2 = (const float*)d_in[4];
    const float* b2 = (const float*)d_in[5];
    float* out = (float*)d_out;

    float *xw, *h, *hw, *wt1, *wt2;
    cudaGetSymbolAddress((void**)&xw, g_xw);
    cudaGetSymbolAddress((void**)&h,  g_h);
    cudaGetSymbolAddress((void**)&hw, g_hw);
    cudaGetSymbolAddress((void**)&wt1, g_wt1);
    cudaGetSymbolAddress((void**)&wt2, g_wt2);

    // kernel_launch runs only a handful of times (correctness + capture), so
    // per-call stream/event creation is cheap and never destroyed mid-capture.
    cudaStream_t s1;
    cudaEvent_t eFork, eJoin;
    cudaStreamCreateWithFlags(&s1, cudaStreamNonBlocking);
    cudaEventCreateWithFlags(&eFork, cudaEventDisableTiming);
    cudaEventCreateWithFlags(&eJoin, cudaEventDisableTiming);

    // fork
    cudaEventRecord(eFork, 0);
    cudaStreamWaitEvent(s1, eFork, 0);

    // graph-stream (s1): CSR build
    k_hist<<<(N_EDGES + 255) / 256, 256, 0, s1>>>(ei);
    k_scan1<<<NB_SCAN, 1024, 0, s1>>>();
    k_scan23<<<NB_SCAN, 1024, 0, s1>>>();
    k_fill<<<(N_EDGES + 255) / 256, 256, 0, s1>>>(ei);
    cudaEventRecord(eJoin, s1);

    // gemm-stream (default): weights + layer-1 GEMM (graph-independent)
    k_prep_w<<<(IN_CH * HID + 255) / 256, 256>>>(W1, W2);
    k_gemm<HID, IN_CH><<<(N_NODES + 127) / 128, 256>>>(x, wt1, xw, N_NODES);

    // join, then the serial tail
    cudaStreamWaitEvent(0, eJoin, 0);
    k_agg1<<<(N_NODES * 32 + 255) / 256, 256>>>(b1);
    k_gemm<OUT_CH, HID><<<(N_NODES + 127) / 128, 256>>>(h, wt2, hw, N_NODES);
    k_agg2<<<(N_NODES * 32 + 255) / 256, 256>>>(b2, out);
}

// round 6
// speedup vs baseline: 1.9429x; 1.0867x over previous
#include <cuda_runtime.h>
#include <cuda_fp16.h>
#include <cstdint>
#include <cstddef>

#define N_NODES 100000
#define N_EDGES 1600000
#define IN_CH   256
#define HID     128
#define OUT_CH  64
#define NB_SCAN ((N_NODES + 1023) / 1024)   // 98

// ---------------- scratch (no allocs allowed) ----------------
__device__ int    g_cnt[N_NODES];           // zero at load; re-zeroed by agg2 tail each call
__device__ int    g_rowptr[N_NODES + 1];
__device__ int    g_part[128];
__device__ int    g_col[N_EDGES];
__device__ float  g_dinv[N_NODES];
__device__ float  g_wt1[HID * IN_CH];       // W1^T, tf32-rounded
__device__ float  g_wt2[OUT_CH * HID];      // W2^T, tf32-rounded
__device__ __half g_xw[(size_t)N_NODES * HID];     // x @ W1, fp16 (gather buffer)
__device__ float  g_h [(size_t)N_NODES * HID];     // relu(layer1), fp32 (streamed)
__device__ __half g_hw[(size_t)N_NODES * OUT_CH];  // h @ W2, fp16 (gather buffer)

// ---------------- small PTX helpers ----------------
__device__ __forceinline__ uint32_t smem_u32(const void* p) {
    return (uint32_t)__cvta_generic_to_shared(p);
}
__device__ __forceinline__ void cp16(uint32_t dst, const void* src, bool pred) {
    asm volatile("cp.async.cg.shared.global [%0], [%1], 16, %2;"
                 :: "r"(dst), "l"(src), "r"(pred ? 16 : 0));
}
__device__ __forceinline__ void cp_commit() { asm volatile("cp.async.commit_group;"); }
template <int N>
__device__ __forceinline__ void cp_wait() { asm volatile("cp.async.wait_group %0;" :: "n"(N)); }

__device__ __forceinline__ void ldsm4(uint32_t& r0, uint32_t& r1, uint32_t& r2, uint32_t& r3,
                                      uint32_t addr) {
    asm volatile("ldmatrix.sync.aligned.m8n8.x4.b16 {%0,%1,%2,%3}, [%4];"
                 : "=r"(r0), "=r"(r1), "=r"(r2), "=r"(r3) : "r"(addr));
}
__device__ __forceinline__ void mma_tf32(float* c, const uint32_t* a, const uint32_t* b) {
    asm volatile("mma.sync.aligned.m16n8k8.row.col.f32.tf32.tf32.f32 "
                 "{%0,%1,%2,%3}, {%4,%5,%6,%7}, {%8,%9}, {%0,%1,%2,%3};"
                 : "+f"(c[0]), "+f"(c[1]), "+f"(c[2]), "+f"(c[3])
                 : "r"(a[0]), "r"(a[1]), "r"(a[2]), "r"(a[3]), "r"(b[0]), "r"(b[1]));
}
__device__ __forceinline__ uint32_t to_tf32(uint32_t x) {
    float f = __uint_as_float(x);
    uint32_t o;
    asm("cvt.rna.tf32.f32 %0, %1;" : "=r"(o) : "f"(f));
    return o;
}
__device__ __forceinline__ float round_tf32_f(float f) {
    uint32_t o;
    asm("cvt.rna.tf32.f32 %0, %1;" : "=r"(o) : "f"(f));
    return __uint_as_float(o);
}

// ---------------- weight transpose/round (gemm-stream) ----------------
__global__ void k_prep_w(const float* __restrict__ W1, const float* __restrict__ W2) {
    int i = blockIdx.x * blockDim.x + threadIdx.x;
    if (i < IN_CH * HID) {             // W1 [256][128] -> Wt1 [128][256]
        int k = i / HID, n = i % HID;
        g_wt1[n * IN_CH + k] = round_tf32_f(W1[i]);
    }
    if (i < HID * OUT_CH) {            // W2 [128][64] -> Wt2 [64][128]
        int k = i / OUT_CH, n = i % OUT_CH;
        g_wt2[n * HID + k] = round_tf32_f(W2[i]);
    }
}

// ---------------- degree / CSR build (graph-stream) ----------------
__global__ void k_hist(const int* __restrict__ ei) {
    int e = blockIdx.x * blockDim.x + threadIdx.x;
    if (e < N_EDGES) atomicAdd(&g_cnt[ei[N_EDGES + e]], 1);
}

__global__ void k_scan1() {
    __shared__ int warpsum[32];
    int i = blockIdx.x * 1024 + threadIdx.x;
    int lane = threadIdx.x & 31, wid = threadIdx.x >> 5;
    int c = (i < N_NODES) ? g_cnt[i] : 0;
    if (i < N_NODES) g_dinv[i] = rsqrtf((float)c + 1.0f);  // +1 self loop
    int x = c;
    #pragma unroll
    for (int d = 1; d < 32; d <<= 1) {
        int y = __shfl_up_sync(0xFFFFFFFFu, x, d);
        if (lane >= d) x += y;
    }
    if (lane == 31) warpsum[wid] = x;
    __syncthreads();
    if (wid == 0) {
        int s = warpsum[lane];
        #pragma unroll
        for (int d = 1; d < 32; d <<= 1) {
            int y = __shfl_up_sync(0xFFFFFFFFu, s, d);
            if (lane >= d) s += y;
        }
        warpsum[lane] = s;
    }
    __syncthreads();
    int incl = x + (wid > 0 ? warpsum[wid - 1] : 0);
    if (i < N_NODES) g_rowptr[i + 1] = incl;
    if (threadIdx.x == 1023) g_part[blockIdx.x] = incl;
}

// fused scan2+scan3: every block redundantly scans the 98 partials in smem
__global__ void k_scan23() {
    __shared__ int parts[128];
    int tid = threadIdx.x;
    if (tid < 128) parts[tid] = (tid < NB_SCAN) ? g_part[tid] : 0;
    __syncthreads();
    #pragma unroll
    for (int d = 1; d < 128; d <<= 1) {
        int t = (tid < 128 && tid >= d) ? parts[tid - d] : 0;
        __syncthreads();
        if (tid < 128) parts[tid] += t;
        __syncthreads();
    }
    int base = (blockIdx.x > 0) ? parts[blockIdx.x - 1] : 0;  // exclusive prefix
    int i = blockIdx.x * 1024 + tid;
    if (i < N_NODES) {
        g_rowptr[i + 1] += base;
        g_cnt[i] = 0;  // reset for fill
    }
    if (i == 0) g_rowptr[0] = 0;
}

__global__ void k_fill(const int* __restrict__ ei) {
    int e = blockIdx.x * blockDim.x + threadIdx.x;
    if (e < N_EDGES) {
        int src = ei[e];
        int dst = ei[N_EDGES + e];
        int pos = g_rowptr[dst] + atomicAdd(&g_cnt[dst], 1);
        g_col[pos] = src;
    }
}

// ---------------- tf32 tensor-core GEMM: C[M,BN] = A[M,KDIM] @ Wt^T, fp16 out ----------------
template <int BN, int KDIM>
__global__ void __launch_bounds__(256) k_gemm(const float* __restrict__ A,
                                              const float* __restrict__ Wt,
                                              __half* __restrict__ C, int M) {
    constexpr int BM = 128, BK = 16;
    constexpr int NK = KDIM / BK;
    constexpr int LDSW = 20;             // 16 + 4 pad -> conflict-free ldmatrix
    constexpr int N_TILES = BN / 16;
    __shared__ float As[2][BM][LDSW];
    __shared__ float Bs[2][BN][LDSW];

    const int tid = threadIdx.x;
    const int lane = tid & 31, wid = tid >> 5;
    const int wm = (wid & 3) * 32;
    const int wn = (wid >> 2) * (BN / 2);
    const int m0 = blockIdx.x * BM;

    float acc[2][N_TILES][4];
    #pragma unroll
    for (int mt = 0; mt < 2; mt++)
        #pragma unroll
        for (int nt = 0; nt < N_TILES; nt++)
            #pragma unroll
            for (int r = 0; r < 4; r++) acc[mt][nt][r] = 0.f;

    #define LOAD_TILE(T, BUF)                                                        \
    {                                                                                \
        const int k0_ = (T) * BK;                                                    \
        _Pragma("unroll")                                                            \
        for (int l = 0; l < 2; l++) {                                                \
            int q = tid + l * 256;                                                   \
            int row = q >> 2, kq = q & 3;                                            \
            cp16(smem_u32(&As[BUF][row][kq * 4]),                                    \
                 A + (size_t)(m0 + row) * KDIM + k0_ + kq * 4, (m0 + row) < M);      \
        }                                                                            \
        _Pragma("unroll")                                                            \
        for (int l = 0; l < BN / 64; l++) {                                          \
            int q = tid + l * 256;                                                   \
            int n = q >> 2, kq = q & 3;                                              \
            cp16(smem_u32(&Bs[BUF][n][kq * 4]),                                      \
                 Wt + (size_t)n * KDIM + k0_ + kq * 4, true);                        \
        }                                                                            \
        cp_commit();                                                                 \
    }

    LOAD_TILE(0, 0);
    int buf = 0;
    for (int t = 0; t < NK; t++) {
        if (t + 1 < NK) { LOAD_TILE(t + 1, buf ^ 1); cp_wait<1>(); }
        else            { cp_wait<0>(); }
        __syncthreads();

        #pragma unroll
        for (int ks = 0; ks < 2; ks++) {
            const int kb = ks * 8;
            uint32_t a[2][4];
            #pragma unroll
            for (int mt = 0; mt < 2; mt++) {
                int row = wm + mt * 16 + (lane & 15);
                int col = kb + ((lane & 16) >> 2);
                ldsm4(a[mt][0], a[mt][1], a[mt][2], a[mt][3],
                      smem_u32(&As[buf][row][col]));
                #pragma unroll
                for (int r = 0; r < 4; r++) a[mt][r] = to_tf32(a[mt][r]);
            }
            uint32_t b[N_TILES][2];
            #pragma unroll
            for (int np = 0; np < N_TILES / 2; np++) {
                int row = wn + np * 16 + (lane & 7) + ((lane & 16) >> 1);
                int col = kb + ((lane & 8) >> 1);
                uint32_t r0, r1, r2, r3;
                ldsm4(r0, r1, r2, r3, smem_u32(&Bs[buf][row][col]));
                b[2 * np][0] = r0; b[2 * np][1] = r1;
                b[2 * np + 1][0] = r2; b[2 * np + 1][1] = r3;
            }
            #pragma unroll
            for (int mt = 0; mt < 2; mt++)
                #pragma unroll
                for (int nt = 0; nt < N_TILES; nt++)
                    mma_tf32(acc[mt][nt], a[mt], b[nt]);
        }
        __syncthreads();
        buf ^= 1;
    }
    #undef LOAD_TILE

    #pragma unroll
    for (int mt = 0; mt < 2; mt++) {
        int r0 = m0 + wm + mt * 16 + (lane >> 2);
        #pragma unroll
        for (int nt = 0; nt < N_TILES; nt++) {
            int cix = wn + nt * 8 + (lane & 3) * 2;
            if (r0 < M)
                *(__half2*)&C[(size_t)r0 * BN + cix] =
                    __floats2half2_rn(acc[mt][nt][0], acc[mt][nt][1]);
            if (r0 + 8 < M)
                *(__half2*)&C[(size_t)(r0 + 8) * BN + cix] =
                    __floats2half2_rn(acc[mt][nt][2], acc[mt][nt][3]);
        }
    }
}

// ---------------- warp-per-node aggregation (fp16 in, fp32 accum/out) ----------------
// out[v] = act( dinv[v] * ( dinv[v]*in[v] + sum_s dinv[s]*in[s] ) + bias )
__device__ __forceinline__ void h2acc(float* acc, uint32_t u0, float d) {
    float2 f = __half22float2(*(const __half2*)&u0);
    acc[0] += f.x * d; acc[1] += f.y * d;
}

template <int CH, bool RELU, bool ZERO_CNT>
__device__ __forceinline__ void agg_core(const __half* __restrict__ in,
                                         const float* __restrict__ bias,
                                         float* __restrict__ out) {
    int w = (int)((blockIdx.x * (size_t)blockDim.x + threadIdx.x) >> 5);
    if (w >= N_NODES) return;
    int lane = threadIdx.x & 31;
    constexpr int V = CH / 32;  // halves per lane: 4 (CH=128) or 2 (CH=64)

    if (ZERO_CNT && lane == 0) g_cnt[w] = 0;  // restore invariant for next call

    float dv = g_dinv[w];
    float acc[V] = {};
    {
        const __half* p = in + (size_t)w * CH + lane * V;
        if (V == 4) { uint2 u = *(const uint2*)p; h2acc(acc, u.x, dv); h2acc(acc + 2, u.y, dv); }
        else        { uint32_t u = *(const uint32_t*)p; h2acc(acc, u, dv); }
    }
    int s = g_rowptr[w], e = g_rowptr[w + 1];
    int i = s;
    int e4 = s + ((e - s) & ~3);
    for (; i < e4; i += 4) {
        int c0 = __ldg(&g_col[i]),     c1 = __ldg(&g_col[i + 1]);
        int c2 = __ldg(&g_col[i + 2]), c3 = __ldg(&g_col[i + 3]);
        float d0 = __ldg(&g_dinv[c0]), d1 = __ldg(&g_dinv[c1]);
        float d2 = __ldg(&g_dinv[c2]), d3 = __ldg(&g_dinv[c3]);
        if (V == 4) {
            uint2 u0 = *(const uint2*)(in + (size_t)c0 * CH + lane * 4);
            uint2 u1 = *(const uint2*)(in + (size_t)c1 * CH + lane * 4);
            uint2 u2 = *(const uint2*)(in + (size_t)c2 * CH + lane * 4);
            uint2 u3 = *(const uint2*)(in + (size_t)c3 * CH + lane * 4);
            h2acc(acc, u0.x, d0); h2acc(acc + 2, u0.y, d0);
            h2acc(acc, u1.x, d1); h2acc(acc + 2, u1.y, d1);
            h2acc(acc, u2.x, d2); h2acc(acc + 2, u2.y, d2);
            h2acc(acc, u3.x, d3); h2acc(acc + 2, u3.y, d3);
        } else {
            uint32_t u0 = *(const uint32_t*)(in + (size_t)c0 * CH + lane * 2);
            uint32_t u1 = *(const uint32_t*)(in + (size_t)c1 * CH + lane * 2);
            uint32_t u2 = *(const uint32_t*)(in + (size_t)c2 * CH + lane * 2);
            uint32_t u3 = *(const uint32_t*)(in + (size_t)c3 * CH + lane * 2);
            h2acc(acc, u0, d0); h2acc(acc, u1, d1);
            h2acc(acc, u2, d2); h2acc(acc, u3, d3);
        }
    }
    for (; i < e; i++) {
        int c = __ldg(&g_col[i]);
        float d = __ldg(&g_dinv[c]);
        const __half* p = in + (size_t)c * CH + lane * V;
        if (V == 4) { uint2 u = *(const uint2*)p; h2acc(acc, u.x, d); h2acc(acc + 2, u.y, d); }
        else        { uint32_t u = *(const uint32_t*)p; h2acc(acc, u, d); }
    }
    #pragma unroll
    for (int c = 0; c < V; c++) {
        float r = acc[c] * dv + __ldg(bias + lane * V + c);
        if (RELU) r = fmaxf(r, 0.f);
        acc[c] = r;
    }
    float* q = out + (size_t)w * CH + lane * V;
    if (V == 4) *(float4*)q = make_float4(acc[0], acc[1], acc[2], acc[3]);
    else        *(float2*)q = make_float2(acc[0], acc[1]);
}

__global__ void k_agg1(const float* __restrict__ b1) { agg_core<HID, true, false>(g_xw, b1, g_h); }
__global__ void k_agg2(const float* __restrict__ b2, float* __restrict__ out) {
    agg_core<OUT_CH, false, true>(g_hw, b2, out);
}

// ---------------- launch (forked capture: CSR chain || prep+gemm1) ----------------
extern "C" void kernel_launch(void* const* d_in, const int* in_sizes, int n_in,
                              void* d_out, int out_size) {
    const float* x  = (const float*)d_in[0];
    const int*   ei = (const int*)d_in[1];
    const float* W1 = (const float*)d_in[2];
    const float* b1 = (const float*)d_in[3];
    const float* W2 = (const float*)d_in[4];
    const float* b2 = (const float*)d_in[5];
    float* out = (float*)d_out;

    __half *xw, *hw;
    float *h, *wt1, *wt2;
    cudaGetSymbolAddress((void**)&xw, g_xw);
    cudaGetSymbolAddress((void**)&h,  g_h);
    cudaGetSymbolAddress((void**)&hw, g_hw);
    cudaGetSymbolAddress((void**)&wt1, g_wt1);
    cudaGetSymbolAddress((void**)&wt2, g_wt2);

    cudaStream_t s1;
    cudaEvent_t eFork, eJoin;
    cudaStreamCreateWithFlags(&s1, cudaStreamNonBlocking);
    cudaEventCreateWithFlags(&eFork, cudaEventDisableTiming);
    cudaEventCreateWithFlags(&eJoin, cudaEventDisableTiming);

    // fork
    cudaEventRecord(eFork, 0);
    cudaStreamWaitEvent(s1, eFork, 0);

    // graph-stream (s1): CSR build
    k_hist<<<(N_EDGES + 255) / 256, 256, 0, s1>>>(ei);
    k_scan1<<<NB_SCAN, 1024, 0, s1>>>();
    k_scan23<<<NB_SCAN, 1024, 0, s1>>>();
    k_fill<<<(N_EDGES + 255) / 256, 256, 0, s1>>>(ei);
    cudaEventRecord(eJoin, s1);

    // gemm-stream (default): weights + layer-1 GEMM (graph-independent)
    k_prep_w<<<(IN_CH * HID + 255) / 256, 256>>>(W1, W2);
    k_gemm<HID, IN_CH><<<(N_NODES + 127) / 128, 256>>>(x, wt1, xw, N_NODES);

    // join, then the serial tail
    cudaStreamWaitEvent(0, eJoin, 0);
    k_agg1<<<(N_NODES * 32 + 255) / 256, 256>>>(b1);
    k_gemm<OUT_CH, HID><<<(N_NODES + 127) / 128, 256>>>(h, wt2, hw, N_NODES);
    k_agg2<<<(N_NODES * 32 + 255) / 256, 256>>>(b2, out);
}

// round 9
// speedup vs baseline: 2.0311x; 1.0454x over previous
#include <cuda_runtime.h>
#include <cuda_fp16.h>
#include <cstdint>
#include <cstddef>

#define N_NODES 100000
#define N_EDGES 1600000
#define IN_CH   256
#define HID     128
#define OUT_CH  64
#define NB_SCAN ((N_NODES + 1023) / 1024)   // 98

// ---------------- scratch (no allocs allowed) ----------------
__device__ int    g_cnt[N_NODES];           // zero at load; re-zeroed by agg2 tail each call
__device__ int    g_rowptr[N_NODES + 1];
__device__ int    g_part[128];
__device__ int    g_col[N_EDGES];
__device__ float  g_dinv[N_NODES];
__device__ float  g_wt1[HID * IN_CH];       // W1^T, tf32-rounded
__device__ __half g_wt2h[OUT_CH * HID];     // W2^T, fp16
__device__ __half g_xw[(size_t)N_NODES * HID];     // x @ W1, fp16
__device__ __half g_h [(size_t)N_NODES * HID];     // relu(layer1), fp16
__device__ __half g_hw[(size_t)N_NODES * OUT_CH];  // h @ W2, fp16

// ---------------- small PTX helpers ----------------
__device__ __forceinline__ uint32_t smem_u32(const void* p) {
    return (uint32_t)__cvta_generic_to_shared(p);
}
__device__ __forceinline__ void cp16(uint32_t dst, const void* src, bool pred) {
    asm volatile("cp.async.cg.shared.global [%0], [%1], 16, %2;"
                 :: "r"(dst), "l"(src), "r"(pred ? 16 : 0));
}
__device__ __forceinline__ void cp_commit() { asm volatile("cp.async.commit_group;"); }
template <int N>
__device__ __forceinline__ void cp_wait() { asm volatile("cp.async.wait_group %0;" :: "n"(N)); }

__device__ __forceinline__ void ldsm4(uint32_t& r0, uint32_t& r1, uint32_t& r2, uint32_t& r3,
                                      uint32_t addr) {
    asm volatile("ldmatrix.sync.aligned.m8n8.x4.b16 {%0,%1,%2,%3}, [%4];"
                 : "=r"(r0), "=r"(r1), "=r"(r2), "=r"(r3) : "r"(addr));
}
__device__ __forceinline__ void mma_tf32(float* c, const uint32_t* a, const uint32_t* b) {
    asm volatile("mma.sync.aligned.m16n8k8.row.col.f32.tf32.tf32.f32 "
                 "{%0,%1,%2,%3}, {%4,%5,%6,%7}, {%8,%9}, {%0,%1,%2,%3};"
                 : "+f"(c[0]), "+f"(c[1]), "+f"(c[2]), "+f"(c[3])
                 : "r"(a[0]), "r"(a[1]), "r"(a[2]), "r"(a[3]), "r"(b[0]), "r"(b[1]));
}
__device__ __forceinline__ void mma_f16(float* c, const uint32_t* a, const uint32_t* b) {
    asm volatile("mma.sync.aligned.m16n8k16.row.col.f32.f16.f16.f32 "
                 "{%0,%1,%2,%3}, {%4,%5,%6,%7}, {%8,%9}, {%0,%1,%2,%3};"
                 : "+f"(c[0]), "+f"(c[1]), "+f"(c[2]), "+f"(c[3])
                 : "r"(a[0]), "r"(a[1]), "r"(a[2]), "r"(a[3]), "r"(b[0]), "r"(b[1]));
}
__device__ __forceinline__ uint32_t to_tf32(uint32_t x) {
    float f = __uint_as_float(x);
    uint32_t o;
    asm("cvt.rna.tf32.f32 %0, %1;" : "=r"(o) : "f"(f));
    return o;
}
__device__ __forceinline__ float round_tf32_f(float f) {
    uint32_t o;
    asm("cvt.rna.tf32.f32 %0, %1;" : "=r"(o) : "f"(f));
    return __uint_as_float(o);
}

// ---------------- weight transpose/round (gemm-stream) ----------------
__global__ void k_prep_w(const float* __restrict__ W1, const float* __restrict__ W2) {
    int i = blockIdx.x * blockDim.x + threadIdx.x;
    if (i < IN_CH * HID) {             // W1 [256][128] -> Wt1 [128][256], tf32
        int k = i / HID, n = i % HID;
        g_wt1[n * IN_CH + k] = round_tf32_f(W1[i]);
    }
    if (i < HID * OUT_CH) {            // W2 [128][64] -> Wt2h [64][128], fp16
        int k = i / OUT_CH, n = i % OUT_CH;
        g_wt2h[n * HID + k] = __float2half_rn(W2[i]);
    }
}

// ---------------- degree / CSR build (graph-stream) ----------------
__global__ void k_hist(const int* __restrict__ ei) {
    int e = blockIdx.x * blockDim.x + threadIdx.x;
    if (e < N_EDGES) atomicAdd(&g_cnt[ei[N_EDGES + e]], 1);
}

__global__ void k_scan1() {
    __shared__ int warpsum[32];
    int i = blockIdx.x * 1024 + threadIdx.x;
    int lane = threadIdx.x & 31, wid = threadIdx.x >> 5;
    int c = (i < N_NODES) ? g_cnt[i] : 0;
    if (i < N_NODES) g_dinv[i] = rsqrtf((float)c + 1.0f);  // +1 self loop
    int x = c;
    #pragma unroll
    for (int d = 1; d < 32; d <<= 1) {
        int y = __shfl_up_sync(0xFFFFFFFFu, x, d);
        if (lane >= d) x += y;
    }
    if (lane == 31) warpsum[wid] = x;
    __syncthreads();
    if (wid == 0) {
        int s = warpsum[lane];
        #pragma unroll
        for (int d = 1; d < 32; d <<= 1) {
            int y = __shfl_up_sync(0xFFFFFFFFu, s, d);
            if (lane >= d) s += y;
        }
        warpsum[lane] = s;
    }
    __syncthreads();
    int incl = x + (wid > 0 ? warpsum[wid - 1] : 0);
    if (i < N_NODES) g_rowptr[i + 1] = incl;
    if (threadIdx.x == 1023) g_part[blockIdx.x] = incl;
}

// fused scan2+scan3: every block redundantly scans the 98 partials in smem
__global__ void k_scan23() {
    __shared__ int parts[128];
    int tid = threadIdx.x;
    if (tid < 128) parts[tid] = (tid < NB_SCAN) ? g_part[tid] : 0;
    __syncthreads();
    #pragma unroll
    for (int d = 1; d < 128; d <<= 1) {
        int t = (tid < 128 && tid >= d) ? parts[tid - d] : 0;
        __syncthreads();
        if (tid < 128) parts[tid] += t;
        __syncthreads();
    }
    int base = (blockIdx.x > 0) ? parts[blockIdx.x - 1] : 0;  // exclusive prefix
    int i = blockIdx.x * 1024 + tid;
    if (i < N_NODES) {
        g_rowptr[i + 1] += base;
        g_cnt[i] = 0;  // reset for fill
    }
    if (i == 0) g_rowptr[0] = 0;
}

__global__ void k_fill(const int* __restrict__ ei) {
    int e = blockIdx.x * blockDim.x + threadIdx.x;
    if (e < N_EDGES) {
        int src = ei[e];
        int dst = ei[N_EDGES + e];
        int pos = g_rowptr[dst] + atomicAdd(&g_cnt[dst], 1);
        g_col[pos] = src;
    }
}

// ---------------- tf32 tensor-core GEMM1: C[M,128] = A[M,256] @ Wt1^T, fp16 out ----------------
template <int BN, int KDIM>
__global__ void __launch_bounds__(256) k_gemm(const float* __restrict__ A,
                                              const float* __restrict__ Wt,
                                              __half* __restrict__ C, int M) {
    constexpr int BM = 128, BK = 16;
    constexpr int NK = KDIM / BK;
    constexpr int LDSW = 20;             // 16 + 4 pad -> conflict-free ldmatrix
    constexpr int N_TILES = BN / 16;
    __shared__ float As[2][BM][LDSW];
    __shared__ float Bs[2][BN][LDSW];

    const int tid = threadIdx.x;
    const int lane = tid & 31, wid = tid >> 5;
    const int wm = (wid & 3) * 32;
    const int wn = (wid >> 2) * (BN / 2);
    const int m0 = blockIdx.x * BM;

    float acc[2][N_TILES][4];
    #pragma unroll
    for (int mt = 0; mt < 2; mt++)
        #pragma unroll
        for (int nt = 0; nt < N_TILES; nt++)
            #pragma unroll
            for (int r = 0; r < 4; r++) acc[mt][nt][r] = 0.f;

    #define LOAD_TILE(T, BUF)                                                        \
    {                                                                                \
        const int k0_ = (T) * BK;                                                    \
        _Pragma("unroll")                                                            \
        for (int l = 0; l < 2; l++) {                                                \
            int q = tid + l * 256;                                                   \
            int row = q >> 2, kq = q & 3;                                            \
            cp16(smem_u32(&As[BUF][row][kq * 4]),                                    \
                 A + (size_t)(m0 + row) * KDIM + k0_ + kq * 4, (m0 + row) < M);      \
        }                                                                            \
        _Pragma("unroll")                                                            \
        for (int l = 0; l < BN / 64; l++) {                                          \
            int q = tid + l * 256;                                                   \
            int n = q >> 2, kq = q & 3;                                              \
            cp16(smem_u32(&Bs[BUF][n][kq * 4]),                                      \
                 Wt + (size_t)n * KDIM + k0_ + kq * 4, true);                        \
        }                                                                            \
        cp_commit();                                                                 \
    }

    LOAD_TILE(0, 0);
    int buf = 0;
    for (int t = 0; t < NK; t++) {
        if (t + 1 < NK) { LOAD_TILE(t + 1, buf ^ 1); cp_wait<1>(); }
        else            { cp_wait<0>(); }
        __syncthreads();

        #pragma unroll
        for (int ks = 0; ks < 2; ks++) {
            const int kb = ks * 8;
            uint32_t a[2][4];
            #pragma unroll
            for (int mt = 0; mt < 2; mt++) {
                int row = wm + mt * 16 + (lane & 15);
                int col = kb + ((lane & 16) >> 2);
                ldsm4(a[mt][0], a[mt][1], a[mt][2], a[mt][3],
                      smem_u32(&As[buf][row][col]));
                #pragma unroll
                for (int r = 0; r < 4; r++) a[mt][r] = to_tf32(a[mt][r]);
            }
            uint32_t b[N_TILES][2];
            #pragma unroll
            for (int np = 0; np < N_TILES / 2; np++) {
                int row = wn + np * 16 + (lane & 7) + ((lane & 16) >> 1);
                int col = kb + ((lane & 8) >> 1);
                uint32_t r0, r1, r2, r3;
                ldsm4(r0, r1, r2, r3, smem_u32(&Bs[buf][row][col]));
                b[2 * np][0] = r0; b[2 * np][1] = r1;
                b[2 * np + 1][0] = r2; b[2 * np + 1][1] = r3;
            }
            #pragma unroll
            for (int mt = 0; mt < 2; mt++)
                #pragma unroll
                for (int nt = 0; nt < N_TILES; nt++)
                    mma_tf32(acc[mt][nt], a[mt], b[nt]);
        }
        __syncthreads();
        buf ^= 1;
    }
    #undef LOAD_TILE

    #pragma unroll
    for (int mt = 0; mt < 2; mt++) {
        int r0 = m0 + wm + mt * 16 + (lane >> 2);
        #pragma unroll
        for (int nt = 0; nt < N_TILES; nt++) {
            int cix = wn + nt * 8 + (lane & 3) * 2;
            if (r0 < M)
                *(__half2*)&C[(size_t)r0 * BN + cix] =
                    __floats2half2_rn(acc[mt][nt][0], acc[mt][nt][1]);
            if (r0 + 8 < M)
                *(__half2*)&C[(size_t)(r0 + 8) * BN + cix] =
                    __floats2half2_rn(acc[mt][nt][2], acc[mt][nt][3]);
        }
    }
}

// ---------------- fp16 GEMM2: C[M,64] = A[M,128](fp16) @ Wt2h^T(fp16), fp16 out ----------------
__global__ void __launch_bounds__(256) k_gemm2h(const __half* __restrict__ A,
                                                const __half* __restrict__ Wt,
                                                __half* __restrict__ C, int M) {
    constexpr int BM = 128, BK = 16;          // k16 per mma step, one step per tile
    constexpr int NK = HID / BK;              // 8
    constexpr int LDS = 24;                   // halves; 48B row stride, conflict-free ldmatrix
    __shared__ __half As[2][BM][LDS];
    __shared__ __half Bs[2][OUT_CH][LDS];

    const int tid = threadIdx.x;
    const int lane = tid & 31, wid = tid >> 5;
    const int wm = (wid & 3) * 32;            // 2 x m16 per warp
    const int wn = (wid >> 2) * 32;           // 4 x n8 per warp
    const int m0 = blockIdx.x * BM;

    float acc[2][4][4];
    #pragma unroll
    for (int mt = 0; mt < 2; mt++)
        #pragma unroll
        for (int nt = 0; nt < 4; nt++)
            #pragma unroll
            for (int r = 0; r < 4; r++) acc[mt][nt][r] = 0.f;

    #define LOAD_TILE2(T, BUF)                                                       \
    {                                                                                \
        const int k0_ = (T) * BK;                                                    \
        {   /* A: 128 rows x 32B = 256 cp16 */                                       \
            int row = tid >> 1, ko = (tid & 1) * 8;                                  \
            cp16(smem_u32(&As[BUF][row][ko]),                                        \
                 A + (size_t)(m0 + row) * HID + k0_ + ko, (m0 + row) < M);           \
        }                                                                            \
        if (tid < 128) { /* B: 64 rows x 32B = 128 cp16 */                           \
            int row = tid >> 1, ko = (tid & 1) * 8;                                  \
            cp16(smem_u32(&Bs[BUF][row][ko]),                                        \
                 Wt + (size_t)row * HID + k0_ + ko, true);                           \
        }                                                                            \
        cp_commit();                                                                 \
    }

    LOAD_TILE2(0, 0);
    int buf = 0;
    for (int t = 0; t < NK; t++) {
        if (t + 1 < NK) { LOAD_TILE2(t + 1, buf ^ 1); cp_wait<1>(); }
        else            { cp_wait<0>(); }
        __syncthreads();

        // A fragments: 2 x (m16 x k16) via ldmatrix.x4
        uint32_t a[2][4];
        #pragma unroll
        for (int mt = 0; mt < 2; mt++) {
            int row = wm + mt * 16 + (lane & 15);
            int col = ((lane >> 4) & 1) * 8;
            ldsm4(a[mt][0], a[mt][1], a[mt][2], a[mt][3], smem_u32(&As[buf][row][col]));
        }
        // B fragments: 4 x (k16 x n8); one ldmatrix.x4 covers 2 n8 tiles
        uint32_t b[4][2];
        #pragma unroll
        for (int np = 0; np < 2; np++) {
            int row = wn + np * 16 + (lane & 7) + (((lane >> 4) & 1) * 8);
            int col = ((lane >> 3) & 1) * 8;
            uint32_t r0, r1, r2, r3;
            ldsm4(r0, r1, r2, r3, smem_u32(&Bs[buf][row][col]));
            b[2 * np][0] = r0;     b[2 * np][1] = r1;
            b[2 * np + 1][0] = r2; b[2 * np + 1][1] = r3;
        }
        #pragma unroll
        for (int mt = 0; mt < 2; mt++)
            #pragma unroll
            for (int nt = 0; nt < 4; nt++)
                mma_f16(acc[mt][nt], a[mt], b[nt]);

        __syncthreads();
        buf ^= 1;
    }
    #undef LOAD_TILE2

    #pragma unroll
    for (int mt = 0; mt < 2; mt++) {
        int r0 = m0 + wm + mt * 16 + (lane >> 2);
        #pragma unroll
        for (int nt = 0; nt < 4; nt++) {
            int cix = wn + nt * 8 + (lane & 3) * 2;
            if (r0 < M)
                *(__half2*)&C[(size_t)r0 * OUT_CH + cix] =
                    __floats2half2_rn(acc[mt][nt][0], acc[mt][nt][1]);
            if (r0 + 8 < M)
                *(__half2*)&C[(size_t)(r0 + 8) * OUT_CH + cix] =
                    __floats2half2_rn(acc[mt][nt][2], acc[mt][nt][3]);
        }
    }
}

// ---------------- warp-per-node aggregation (fp16 in, fp32 accum) ----------------
// out[v] = act( dinv[v] * ( dinv[v]*in[v] + sum_s dinv[s]*in[s] ) + bias )
__device__ __forceinline__ void h2acc(float* acc, uint32_t u0, float d) {
    float2 f = __half22float2(*(const __half2*)&u0);
    acc[0] += f.x * d; acc[1] += f.y * d;
}

template <int CH, bool RELU, bool HALF_OUT, bool ZERO_CNT>
__device__ __forceinline__ void agg_core(const __half* __restrict__ in,
                                         const float* __restrict__ bias,
                                         void* __restrict__ out_p) {
    int w = (int)((blockIdx.x * (size_t)blockDim.x + threadIdx.x) >> 5);
    if (w >= N_NODES) return;
    int lane = threadIdx.x & 31;
    constexpr int V = CH / 32;  // halves per lane: 4 (CH=128) or 2 (CH=64)

    if (ZERO_CNT && lane == 0) g_cnt[w] = 0;  // restore invariant for next call

    float dv = g_dinv[w];
    float acc[V] = {};
    {
        const __half* p = in + (size_t)w * CH + lane * V;
        if (V == 4) { uint2 u = *(const uint2*)p; h2acc(acc, u.x, dv); h2acc(acc + 2, u.y, dv); }
        else        { uint32_t u = *(const uint32_t*)p; h2acc(acc, u, dv); }
    }
    int s = g_rowptr[w], e = g_rowptr[w + 1];
    int i = s;
    int e4 = s + ((e - s) & ~3);
    for (; i < e4; i += 4) {
        int c0 = __ldg(&g_col[i]),     c1 = __ldg(&g_col[i + 1]);
        int c2 = __ldg(&g_col[i + 2]), c3 = __ldg(&g_col[i + 3]);
        float d0 = __ldg(&g_dinv[c0]), d1 = __ldg(&g_dinv[c1]);
        float d2 = __ldg(&g_dinv[c2]), d3 = __ldg(&g_dinv[c3]);
        if (V == 4) {
            uint2 u0 = *(const uint2*)(in + (size_t)c0 * CH + lane * 4);
            uint2 u1 = *(const uint2*)(in + (size_t)c1 * CH + lane * 4);
            uint2 u2 = *(const uint2*)(in + (size_t)c2 * CH + lane * 4);
            uint2 u3 = *(const uint2*)(in + (size_t)c3 * CH + lane * 4);
            h2acc(acc, u0.x, d0); h2acc(acc + 2, u0.y, d0);
            h2acc(acc, u1.x, d1); h2acc(acc + 2, u1.y, d1);
            h2acc(acc, u2.x, d2); h2acc(acc + 2, u2.y, d2);
            h2acc(acc, u3.x, d3); h2acc(acc + 2, u3.y, d3);
        } else {
            uint32_t u0 = *(const uint32_t*)(in + (size_t)c0 * CH + lane * 2);
            uint32_t u1 = *(const uint32_t*)(in + (size_t)c1 * CH + lane * 2);
            uint32_t u2 = *(const uint32_t*)(in + (size_t)c2 * CH + lane * 2);
            uint32_t u3 = *(const uint32_t*)(in + (size_t)c3 * CH + lane * 2);
            h2acc(acc, u0, d0); h2acc(acc, u1, d1);
            h2acc(acc, u2, d2); h2acc(acc, u3, d3);
        }
    }
    for (; i < e; i++) {
        int c = __ldg(&g_col[i]);
        float d = __ldg(&g_dinv[c]);
        const __half* p = in + (size_t)c * CH + lane * V;
        if (V == 4) { uint2 u = *(const uint2*)p; h2acc(acc, u.x, d); h2acc(acc + 2, u.y, d); }
        else        { uint32_t u = *(const uint32_t*)p; h2acc(acc, u, d); }
    }
    #pragma unroll
    for (int c = 0; c < V; c++) {
        float r = acc[c] * dv + __ldg(bias + lane * V + c);
        if (RELU) r = fmaxf(r, 0.f);
        acc[c] = r;
    }
    if (HALF_OUT) {
        __half* q = (__half*)out_p + (size_t)w * CH + lane * V;
        if (V == 4) {
            uint2 u;
            *(__half2*)&u.x = __floats2half2_rn(acc[0], acc[1]);
            *(__half2*)&u.y = __floats2half2_rn(acc[2], acc[3]);
            *(uint2*)q = u;
        } else {
            __half2 u = __floats2half2_rn(acc[0], acc[1]);
            *(__half2*)q = u;
        }
    } else {
        float* q = (float*)out_p + (size_t)w * CH + lane * V;
        if (V == 4) *(float4*)q = make_float4(acc[0], acc[1], acc[2], acc[3]);
        else        *(float2*)q = make_float2(acc[0], acc[1]);
    }
}

__global__ void k_agg1(const float* __restrict__ b1) {
    agg_core<HID, true, true, false>(g_xw, b1, g_h);
}
__global__ void k_agg2(const float* __restrict__ b2, float* __restrict__ out) {
    agg_core<OUT_CH, false, false, true>(g_hw, b2, out);
}

// ---------------- launch (forked capture: CSR chain || prep+gemm1) ----------------
extern "C" void kernel_launch(void* const* d_in, const int* in_sizes, int n_in,
                              void* d_out, int out_size) {
    const float* x  = (const float*)d_in[0];
    const int*   ei = (const int*)d_in[1];
    const float* W1 = (const float*)d_in[2];
    const float* b1 = (const float*)d_in[3];
    const float* W2 = (const float*)d_in[4];
    const float* b2 = (const float*)d_in[5];
    float* out = (float*)d_out;

    __half *xw, *h, *hw, *wt2h;
    float *wt1;
    cudaGetSymbolAddress((void**)&xw, g_xw);
    cudaGetSymbolAddress((void**)&h,  g_h);
    cudaGetSymbolAddress((void**)&hw, g_hw);
    cudaGetSymbolAddress((void**)&wt1, g_wt1);
    cudaGetSymbolAddress((void**)&wt2h, g_wt2h);

    cudaStream_t s1;
    cudaEvent_t eFork, eJoin;
    cudaStreamCreateWithFlags(&s1, cudaStreamNonBlocking);
    cudaEventCreateWithFlags(&eFork, cudaEventDisableTiming);
    cudaEventCreateWithFlags(&eJoin, cudaEventDisableTiming);

    // fork
    cudaEventRecord(eFork, 0);
    cudaStreamWaitEvent(s1, eFork, 0);

    // graph-stream (s1): CSR build
    k_hist<<<(N_EDGES + 255) / 256, 256, 0, s1>>>(ei);
    k_scan1<<<NB_SCAN, 1024, 0, s1>>>();
    k_scan23<<<NB_SCAN, 1024, 0, s1>>>();
    k_fill<<<(N_EDGES + 255) / 256, 256, 0, s1>>>(ei);
    cudaEventRecord(eJoin, s1);

    // gemm-stream (default): weights + layer-1 GEMM (graph-independent)
    k_prep_w<<<(IN_CH * HID + 255) / 256, 256>>>(W1, W2);
    k_gemm<HID, IN_CH><<<(N_NODES + 127) / 128, 256>>>(x, wt1, xw, N_NODES);

    // join, then the serial tail
    cudaStreamWaitEvent(0, eJoin, 0);
    k_agg1<<<(N_NODES * 32 + 255) / 256, 256>>>(b1);
    k_gemm2h<<<(N_NODES + 127) / 128, 256>>>(h, wt2h, hw, N_NODES);
    k_agg2<<<(N_NODES * 32 + 255) / 256, 256>>>(b2, out);
}